// round 6
// baseline (speedup 1.0000x reference)
#include <cuda_runtime.h>
#include <cuda_fp16.h>
#include <cstdint>

// y = gather_perm(x @ Wv) @ Wo^T   (softmax rowsum == 1 collapse, validated R1)
// tcgen05 unavailable (harness targets sm_103, no 'a') => mma.sync path.
// fp16 2-pass asymmetric split  C = Ah*B + Al*B  (rel_err 2.9e-4, validated R5)
// R6: BK=64 chunks (16 iters), SINGLE __syncthreads per chunk
//     (wait; sync; issue; compute), KS=72 conflict-free stride.
//     Targets the barrier/phase-bubble binder (tensor 37.7%, issue 24.9%).

#define MTOT 4096
#define DD   1024
#define BK   64
#define KSB  144                 // smem row stride bytes (72 halves): 36 words -> 4r banks, conflict-free
#define STG_MAT  (128 * KSB)     // 18432 B per matrix tile
#define OFF_AH   0
#define OFF_AL   (1 * STG_MAT)
#define OFF_B    (2 * STG_MAT)
#define STG_BYTES (3 * STG_MAT)  // 55296 B / stage
#define SMEM_SZ   (2 * STG_BYTES)   // 110592 B ; 2 CTAs/SM = 216 KB <= 228 KB
#define NCHUNK   (DD / BK)       // 16

__device__ __half g_xh[MTOT * DD], g_xl[MTOT * DD];
__device__ __half g_wvt[DD * DD];
__device__ __half g_wo[DD * DD];
__device__ __half g_vh[MTOT * DD], g_vl[MTOT * DD];

// ------------------------------------------------------------------ asm utils
static __device__ __forceinline__ uint32_t smem_u32(const void* p) {
    uint32_t a;
    asm("{ .reg .u64 t; cvta.to.shared.u64 t, %1; cvt.u32.u64 %0, t; }" : "=r"(a) : "l"(p));
    return a;
}
#define CP16(s, g) \
    asm volatile("cp.async.cg.shared.global [%0], [%1], 16;" :: "r"(s), "l"(g))
#define CP_COMMIT() asm volatile("cp.async.commit_group;")
#define CP_WAIT0()  asm volatile("cp.async.wait_group 0;")

#define LDSM4(r, addr) \
    asm volatile("ldmatrix.sync.aligned.m8n8.x4.shared.b16 {%0,%1,%2,%3}, [%4];" \
                 : "=r"((r)[0]), "=r"((r)[1]), "=r"((r)[2]), "=r"((r)[3]) : "r"(addr))

#define MMA(d, a, b0, b1) \
    asm volatile("mma.sync.aligned.m16n8k16.row.col.f32.f16.f16.f32 " \
                 "{%0,%1,%2,%3}, {%4,%5,%6,%7}, {%8,%9}, {%0,%1,%2,%3};" \
                 : "+f"((d)[0]), "+f"((d)[1]), "+f"((d)[2]), "+f"((d)[3]) \
                 : "r"((a)[0]), "r"((a)[1]), "r"((a)[2]), "r"((a)[3]), "r"(b0), "r"(b1))

// ------------------------------------------------------------------ GEMM
// MODE 0: V = x @ WvT^T  (A = g_xh/g_xl [m][k], B = g_wvt [n][k]) -> g_vh/g_vl
// MODE 1: out = gather(V) @ Wo^T (A gathered from g_vh/g_vl, B = g_wo) -> fp32
template<int MODE>
__global__ void __launch_bounds__(256, 2)
gemm_hmma(float* __restrict__ outp) {
    extern __shared__ char smem[];
    const uint32_t sb = smem_u32(smem);

    const int tid  = threadIdx.x;
    const int lane = tid & 31, wid = tid >> 5;
    const int bm = blockIdx.y * 128;
    const int bn = blockIdx.x * 128;

    const __half* Ah_ = (MODE == 0) ? g_xh  : g_vh;
    const __half* Al_ = (MODE == 0) ? g_xl  : g_vl;
    const __half* B_  = (MODE == 0) ? g_wvt : g_wo;

    // gather constants (MODE 1): with BK=64 chunks, k>>6 == c exactly.
    const int boff = (bm >> 11) << 11;          // b * 2048
    const int hoff = ((bm & 2047) >> 7) * 64;   // h * 64

    // ---- global -> smem stage loader: 256 threads, 12 CP16 per thread
    const int seg  = tid & 3;        // 16B segment pair {seg, seg+4} of a 128B row
    const int row0 = tid >> 2;       // 0..63

    auto issue = [&](int c) {
        const uint32_t sbase = sb + (uint32_t)(c & 1) * STG_BYTES;
#pragma unroll
        for (int i = 0; i < 2; i++) {
            const int row = row0 + 64 * i;
            size_t aoff;
            if (MODE == 0) {
                aoff = (size_t)(bm + row) * DD + c * BK + seg * 8;
            } else {
                aoff = (size_t)(boff + row * 16 + c) * DD + hoff + seg * 8;
            }
            const size_t bo = (size_t)(bn + row) * DD + c * BK + seg * 8;
            const uint32_t sA = sbase + row * KSB + seg * 16;
            const uint32_t sB = sbase + OFF_B + row * KSB + seg * 16;
            CP16(sA,                Ah_ + aoff);
            CP16(sA + 64,           Ah_ + aoff + 32);
            CP16(sA + OFF_AL,       Al_ + aoff);
            CP16(sA + OFF_AL + 64,  Al_ + aoff + 32);
            CP16(sB,                B_ + bo);
            CP16(sB + 64,           B_ + bo + 32);
        }
        CP_COMMIT();
    };

    // ---- warp tiling: 2(m) x 4(n) warps of 64x32
    const int warp_m = (wid >> 2) * 64;
    const int warp_n = (wid & 3) * 32;
    const int lr = lane & 15;            // ldmatrix row within 16
    const int lcb = (lane >> 4) * 16;    // ldmatrix k-half byte offset

    float acc[4][4][4];
#pragma unroll
    for (int mt = 0; mt < 4; mt++)
#pragma unroll
        for (int j = 0; j < 4; j++)
#pragma unroll
            for (int q = 0; q < 4; q++) acc[mt][j][q] = 0.f;

    issue(0);

    for (int c = 0; c < NCHUNK; c++) {
        CP_WAIT0();
        __syncthreads();
        if (c + 1 < NCHUNK) issue(c + 1);   // after sync: buffer's readers all passed

        const uint32_t sbase = sb + (uint32_t)(c & 1) * STG_BYTES;
#pragma unroll
        for (int kk = 0; kk < 4; kk++) {
            const uint32_t kb = kk * 32 + lcb;  // k byte offset within 128B row

            // front-load all fragments for this k16 step (10 independent LDSM)
            uint32_t ah[4][4], al[4][4], bb[2][4];
#pragma unroll
            for (int mt = 0; mt < 4; mt++) {
                const uint32_t aAddr = sbase + (warp_m + mt * 16 + lr) * KSB + kb;
                LDSM4(ah[mt], aAddr + OFF_AH);
                LDSM4(al[mt], aAddr + OFF_AL);
            }
#pragma unroll
            for (int nt = 0; nt < 2; nt++) {
                const uint32_t bAddr = sbase + OFF_B +
                                       (warp_n + nt * 16 + lr) * KSB + kb;
                LDSM4(bb[nt], bAddr);
            }

            // pass 1: Ah x B
#pragma unroll
            for (int mt = 0; mt < 4; mt++)
#pragma unroll
                for (int nt = 0; nt < 2; nt++) {
                    MMA(acc[mt][2 * nt],     ah[mt], bb[nt][0], bb[nt][2]);
                    MMA(acc[mt][2 * nt + 1], ah[mt], bb[nt][1], bb[nt][3]);
                }
            // pass 2: Al x B (all regs retained)
#pragma unroll
            for (int mt = 0; mt < 4; mt++)
#pragma unroll
                for (int nt = 0; nt < 2; nt++) {
                    MMA(acc[mt][2 * nt],     al[mt], bb[nt][0], bb[nt][2]);
                    MMA(acc[mt][2 * nt + 1], al[mt], bb[nt][1], bb[nt][3]);
                }
        }
    }

    // ---- epilogue (fragment layout: d0,d1 -> row lane>>2, d2,d3 -> +8)
#pragma unroll
    for (int mt = 0; mt < 4; mt++) {
        const int m0 = bm + warp_m + mt * 16 + (lane >> 2);
#pragma unroll
        for (int j = 0; j < 4; j++) {
            const int n0 = bn + warp_n + j * 8 + (lane & 3) * 2;
            const float* d = acc[mt][j];
            if (MODE == 0) {
#pragma unroll
                for (int half_ = 0; half_ < 2; half_++) {
                    const size_t o = (size_t)(m0 + 8 * half_) * DD + n0;
                    float f0 = d[2 * half_], f1 = d[2 * half_ + 1];
                    __half h0 = __float2half_rn(f0);
                    __half h1 = __float2half_rn(f1);
                    __half l0 = __float2half_rn(f0 - __half2float(h0));
                    __half l1 = __float2half_rn(f1 - __half2float(h1));
                    *(__half2*)&g_vh[o] = __halves2half2(h0, h1);
                    *(__half2*)&g_vl[o] = __halves2half2(l0, l1);
                }
            } else {
#pragma unroll
                for (int half_ = 0; half_ < 2; half_++) {
                    const size_t o = (size_t)(m0 + 8 * half_) * DD + n0;
                    *(float2*)&outp[o] = make_float2(d[2 * half_], d[2 * half_ + 1]);
                }
            }
        }
    }
}

// ------------------------------------------------------------------ prep
__global__ void k_split_x(const float* __restrict__ in) {
    const int i = blockIdx.x * 256 + threadIdx.x;   // over float4s
    float4 v = ((const float4*)in)[i];
    __half h0 = __float2half_rn(v.x), h1 = __float2half_rn(v.y);
    __half h2 = __float2half_rn(v.z), h3 = __float2half_rn(v.w);
    __half l0 = __float2half_rn(v.x - __half2float(h0));
    __half l1 = __float2half_rn(v.y - __half2float(h1));
    __half l2 = __float2half_rn(v.z - __half2float(h2));
    __half l3 = __float2half_rn(v.w - __half2float(h3));
    ((__half2*)g_xh)[2 * i]     = __halves2half2(h0, h1);
    ((__half2*)g_xh)[2 * i + 1] = __halves2half2(h2, h3);
    ((__half2*)g_xl)[2 * i]     = __halves2half2(l0, l1);
    ((__half2*)g_xl)[2 * i + 1] = __halves2half2(l2, l3);
}

__global__ void k_conv_wo(const float* __restrict__ in) {
    const int i = blockIdx.x * 256 + threadIdx.x;
    float4 v = ((const float4*)in)[i];
    ((__half2*)g_wo)[2 * i]     = __floats2half2_rn(v.x, v.y);
    ((__half2*)g_wo)[2 * i + 1] = __floats2half2_rn(v.z, v.w);
}

// WvT[n][k] = Wv[k][n], single fp16
__global__ void k_trans_wv(const float* __restrict__ W) {
    __shared__ float t[32][33];
    const int bx = blockIdx.x * 32, by = blockIdx.y * 32;
    const int tx = threadIdx.x, ty = threadIdx.y;   // (32, 8)
#pragma unroll
    for (int j = 0; j < 32; j += 8)
        t[ty + j][tx] = W[(size_t)(by + ty + j) * DD + bx + tx];
    __syncthreads();
#pragma unroll
    for (int j = 0; j < 32; j += 8) {
        const size_t o = (size_t)(bx + ty + j) * DD + by + tx;
        g_wvt[o] = __float2half_rn(t[tx][ty + j]);
    }
}

// ------------------------------------------------------------------ launch
// inputs: x, mask, Wq, Wk, Wv, Wo -> fp32 out [B,T,D]
extern "C" void kernel_launch(void* const* d_in, const int* in_sizes, int n_in,
                              void* d_out, int out_size) {
    const float* x  = (const float*)d_in[0];
    const float* Wv = (const float*)d_in[4];
    const float* Wo = (const float*)d_in[5];
    float* out = (float*)d_out;

    cudaFuncSetAttribute(gemm_hmma<0>, cudaFuncAttributeMaxDynamicSharedMemorySize, SMEM_SZ);
    cudaFuncSetAttribute(gemm_hmma<1>, cudaFuncAttributeMaxDynamicSharedMemorySize, SMEM_SZ);

    k_split_x<<<(MTOT * DD / 4) / 256, 256>>>(x);
    k_trans_wv<<<dim3(32, 32), dim3(32, 8)>>>(Wv);
    k_conv_wo<<<(DD * DD / 4) / 256, 256>>>(Wo);

    dim3 grid(DD / 128, MTOT / 128);   // (8, 32) = 256 CTAs
    gemm_hmma<0><<<grid, 256, SMEM_SZ>>>(nullptr);
    gemm_hmma<1><<<grid, 256, SMEM_SZ>>>(out);
}

// round 7
// speedup vs baseline: 1.1008x; 1.1008x over previous
#include <cuda_runtime.h>
#include <cuda_fp16.h>
#include <cstdint>

// y = gather_perm(x @ Wv) @ Wo^T   (softmax rowsum == 1 collapse, validated R1)
// tcgen05 unavailable (harness targets sm_103, no 'a') => mma.sync path.
// fp16 2-pass asymmetric split  C = Ah*B + Al*B  (rel_err 2.9e-4, validated R5)
// R7: kernel is SMEM-CROSSBAR-BOUND (model: 2560 cyc smem vs 1024 cyc tensor
//     per chunk -> 40% predicted, 37.8% measured; also retrodicts R4's 42.5%).
//     Fix: warp tile 64x64 (4 warps / 128 thr per CTA) cuts LDSM bytes/MMA
//     160 -> 96.  Predicted tensor ~60-65%, total ~100-112us.

#define MTOT 4096
#define DD   1024
#define BK   64
#define KSB  144                 // smem row stride bytes: 36 words -> 4r mod 32 banks, conflict-free
#define STG_MAT  (128 * KSB)     // 18432 B per matrix tile
#define OFF_AH   0
#define OFF_AL   (1 * STG_MAT)
#define OFF_B    (2 * STG_MAT)
#define STG_BYTES (3 * STG_MAT)  // 55296 B / stage
#define SMEM_SZ   (2 * STG_BYTES)   // 110592 B ; 2 CTAs/SM
#define NCHUNK   (DD / BK)       // 16

__device__ __half g_xh[MTOT * DD], g_xl[MTOT * DD];
__device__ __half g_wvt[DD * DD];
__device__ __half g_wo[DD * DD];
__device__ __half g_vh[MTOT * DD], g_vl[MTOT * DD];

// ------------------------------------------------------------------ asm utils
static __device__ __forceinline__ uint32_t smem_u32(const void* p) {
    uint32_t a;
    asm("{ .reg .u64 t; cvta.to.shared.u64 t, %1; cvt.u32.u64 %0, t; }" : "=r"(a) : "l"(p));
    return a;
}
#define CP16(s, g) \
    asm volatile("cp.async.cg.shared.global [%0], [%1], 16;" :: "r"(s), "l"(g))
#define CP_COMMIT() asm volatile("cp.async.commit_group;")
#define CP_WAIT0()  asm volatile("cp.async.wait_group 0;")

#define LDSM4(r, addr) \
    asm volatile("ldmatrix.sync.aligned.m8n8.x4.shared.b16 {%0,%1,%2,%3}, [%4];" \
                 : "=r"((r)[0]), "=r"((r)[1]), "=r"((r)[2]), "=r"((r)[3]) : "r"(addr))

#define MMA(d, a, b0, b1) \
    asm volatile("mma.sync.aligned.m16n8k16.row.col.f32.f16.f16.f32 " \
                 "{%0,%1,%2,%3}, {%4,%5,%6,%7}, {%8,%9}, {%0,%1,%2,%3};" \
                 : "+f"((d)[0]), "+f"((d)[1]), "+f"((d)[2]), "+f"((d)[3]) \
                 : "r"((a)[0]), "r"((a)[1]), "r"((a)[2]), "r"((a)[3]), "r"(b0), "r"(b1))

// ------------------------------------------------------------------ GEMM
// MODE 0: V = x @ WvT^T  (A = g_xh/g_xl [m][k], B = g_wvt [n][k]) -> g_vh/g_vl
// MODE 1: out = gather(V) @ Wo^T (A gathered from g_vh/g_vl, B = g_wo) -> fp32
template<int MODE>
__global__ void __launch_bounds__(128, 2)
gemm_hmma(float* __restrict__ outp) {
    extern __shared__ char smem[];
    const uint32_t sb = smem_u32(smem);

    const int tid  = threadIdx.x;
    const int lane = tid & 31, wid = tid >> 5;
    const int bm = blockIdx.y * 128;
    const int bn = blockIdx.x * 128;

    const __half* Ah_ = (MODE == 0) ? g_xh  : g_vh;
    const __half* Al_ = (MODE == 0) ? g_xl  : g_vl;
    const __half* B_  = (MODE == 0) ? g_wvt : g_wo;

    // gather constants (MODE 1): with BK=64 chunks, k>>6 == c exactly.
    const int boff = (bm >> 11) << 11;          // b * 2048
    const int hoff = ((bm & 2047) >> 7) * 64;   // h * 64

    // ---- global -> smem stage loader: 128 threads, 24 CP16 per thread
    const int seg  = tid & 7;        // 16B segment of 128B row
    const int row0 = tid >> 3;       // 0..15

    auto issue = [&](int c) {
        const uint32_t sbase = sb + (uint32_t)(c & 1) * STG_BYTES;
#pragma unroll
        for (int i = 0; i < 8; i++) {
            const int row = row0 + 16 * i;
            size_t aoff;
            if (MODE == 0) {
                aoff = (size_t)(bm + row) * DD + c * BK + seg * 8;
            } else {
                aoff = (size_t)(boff + row * 16 + c) * DD + hoff + seg * 8;
            }
            const size_t bo = (size_t)(bn + row) * DD + c * BK + seg * 8;
            const uint32_t sA = sbase + row * KSB + seg * 16;
            CP16(sA,           Ah_ + aoff);
            CP16(sA + OFF_AL,  Al_ + aoff);
            CP16(sbase + OFF_B + row * KSB + seg * 16, B_ + bo);
        }
        CP_COMMIT();
    };

    // ---- warp tiling: 2(m) x 2(n) warps of 64x64
    const int warp_m = (wid >> 1) * 64;
    const int warp_n = (wid & 1) * 64;
    const int lr = lane & 15;            // ldmatrix row within 16
    const int lcb = (lane >> 4) * 16;    // ldmatrix k-half byte offset

    float acc[4][8][4];
#pragma unroll
    for (int mt = 0; mt < 4; mt++)
#pragma unroll
        for (int j = 0; j < 8; j++)
#pragma unroll
            for (int q = 0; q < 4; q++) acc[mt][j][q] = 0.f;

    issue(0);

    for (int c = 0; c < NCHUNK; c++) {
        CP_WAIT0();
        __syncthreads();
        if (c + 1 < NCHUNK) issue(c + 1);   // after sync: stage readers all passed

        const uint32_t sbase = sb + (uint32_t)(c & 1) * STG_BYTES;
#pragma unroll
        for (int kk = 0; kk < 4; kk++) {
            const uint32_t kb = kk * 32 + lcb;  // k byte offset within 128B row

            // front-load all fragments for this k16 step (12 independent LDSM)
            uint32_t ah[4][4], al[4][4], bb[4][4];
#pragma unroll
            for (int mt = 0; mt < 4; mt++) {
                const uint32_t aAddr = sbase + (warp_m + mt * 16 + lr) * KSB + kb;
                LDSM4(ah[mt], aAddr + OFF_AH);
                LDSM4(al[mt], aAddr + OFF_AL);
            }
#pragma unroll
            for (int nt = 0; nt < 4; nt++) {
                const uint32_t bAddr = sbase + OFF_B +
                                       (warp_n + nt * 16 + lr) * KSB + kb;
                LDSM4(bb[nt], bAddr);
            }

            // pass 1: Ah x B
#pragma unroll
            for (int mt = 0; mt < 4; mt++)
#pragma unroll
                for (int nt = 0; nt < 4; nt++) {
                    MMA(acc[mt][2 * nt],     ah[mt], bb[nt][0], bb[nt][2]);
                    MMA(acc[mt][2 * nt + 1], ah[mt], bb[nt][1], bb[nt][3]);
                }
            // pass 2: Al x B (all regs retained)
#pragma unroll
            for (int mt = 0; mt < 4; mt++)
#pragma unroll
                for (int nt = 0; nt < 4; nt++) {
                    MMA(acc[mt][2 * nt],     al[mt], bb[nt][0], bb[nt][2]);
                    MMA(acc[mt][2 * nt + 1], al[mt], bb[nt][1], bb[nt][3]);
                }
        }
    }

    // ---- epilogue (fragment layout: d0,d1 -> row lane>>2, d2,d3 -> +8)
#pragma unroll
    for (int mt = 0; mt < 4; mt++) {
        const int m0 = bm + warp_m + mt * 16 + (lane >> 2);
#pragma unroll
        for (int j = 0; j < 8; j++) {
            const int n0 = bn + warp_n + j * 8 + (lane & 3) * 2;
            const float* d = acc[mt][j];
            if (MODE == 0) {
#pragma unroll
                for (int half_ = 0; half_ < 2; half_++) {
                    const size_t o = (size_t)(m0 + 8 * half_) * DD + n0;
                    float f0 = d[2 * half_], f1 = d[2 * half_ + 1];
                    __half h0 = __float2half_rn(f0);
                    __half h1 = __float2half_rn(f1);
                    __half l0 = __float2half_rn(f0 - __half2float(h0));
                    __half l1 = __float2half_rn(f1 - __half2float(h1));
                    *(__half2*)&g_vh[o] = __halves2half2(h0, h1);
                    *(__half2*)&g_vl[o] = __halves2half2(l0, l1);
                }
            } else {
#pragma unroll
                for (int half_ = 0; half_ < 2; half_++) {
                    const size_t o = (size_t)(m0 + 8 * half_) * DD + n0;
                    *(float2*)&outp[o] = make_float2(d[2 * half_], d[2 * half_ + 1]);
                }
            }
        }
    }
}

// ------------------------------------------------------------------ prep
__global__ void k_split_x(const float* __restrict__ in) {
    const int i = blockIdx.x * 256 + threadIdx.x;   // over float4s
    float4 v = ((const float4*)in)[i];
    __half h0 = __float2half_rn(v.x), h1 = __float2half_rn(v.y);
    __half h2 = __float2half_rn(v.z), h3 = __float2half_rn(v.w);
    __half l0 = __float2half_rn(v.x - __half2float(h0));
    __half l1 = __float2half_rn(v.y - __half2float(h1));
    __half l2 = __float2half_rn(v.z - __half2float(h2));
    __half l3 = __float2half_rn(v.w - __half2float(h3));
    ((__half2*)g_xh)[2 * i]     = __halves2half2(h0, h1);
    ((__half2*)g_xh)[2 * i + 1] = __halves2half2(h2, h3);
    ((__half2*)g_xl)[2 * i]     = __halves2half2(l0, l1);
    ((__half2*)g_xl)[2 * i + 1] = __halves2half2(l2, l3);
}

__global__ void k_conv_wo(const float* __restrict__ in) {
    const int i = blockIdx.x * 256 + threadIdx.x;
    float4 v = ((const float4*)in)[i];
    ((__half2*)g_wo)[2 * i]     = __floats2half2_rn(v.x, v.y);
    ((__half2*)g_wo)[2 * i + 1] = __floats2half2_rn(v.z, v.w);
}

// WvT[n][k] = Wv[k][n], single fp16
__global__ void k_trans_wv(const float* __restrict__ W) {
    __shared__ float t[32][33];
    const int bx = blockIdx.x * 32, by = blockIdx.y * 32;
    const int tx = threadIdx.x, ty = threadIdx.y;   // (32, 8)
#pragma unroll
    for (int j = 0; j < 32; j += 8)
        t[ty + j][tx] = W[(size_t)(by + ty + j) * DD + bx + tx];
    __syncthreads();
#pragma unroll
    for (int j = 0; j < 32; j += 8) {
        const size_t o = (size_t)(bx + ty + j) * DD + by + tx;
        g_wvt[o] = __float2half_rn(t[tx][ty + j]);
    }
}

// ------------------------------------------------------------------ launch
// inputs: x, mask, Wq, Wk, Wv, Wo -> fp32 out [B,T,D]
extern "C" void kernel_launch(void* const* d_in, const int* in_sizes, int n_in,
                              void* d_out, int out_size) {
    const float* x  = (const float*)d_in[0];
    const float* Wv = (const float*)d_in[4];
    const float* Wo = (const float*)d_in[5];
    float* out = (float*)d_out;

    cudaFuncSetAttribute(gemm_hmma<0>, cudaFuncAttributeMaxDynamicSharedMemorySize, SMEM_SZ);
    cudaFuncSetAttribute(gemm_hmma<1>, cudaFuncAttributeMaxDynamicSharedMemorySize, SMEM_SZ);

    k_split_x<<<(MTOT * DD / 4) / 256, 256>>>(x);
    k_trans_wv<<<dim3(32, 32), dim3(32, 8)>>>(Wv);
    k_conv_wo<<<(DD * DD / 4) / 256, 256>>>(Wo);

    dim3 grid(DD / 128, MTOT / 128);   // (8, 32) = 256 CTAs
    gemm_hmma<0><<<grid, 128, SMEM_SZ>>>(nullptr);
    gemm_hmma<1><<<grid, 128, SMEM_SZ>>>(out);
}

// round 8
// speedup vs baseline: 1.8798x; 1.7077x over previous
#include <cuda_runtime.h>
#include <cuda_fp16.h>
#include <cstdint>

// y = gather_perm(x @ Wv) @ Wo^T   (softmax rowsum == 1 collapse, validated R1)
// tcgen05 unavailable (harness targets sm_103, no 'a') => mma.sync path.
// R8: cross-round analysis shows a HW ceiling for legacy mma.sync:
//     duration ~= 18-19 cyc * #HMMA/SMSP across ALL configs (R3/R5/R7 =
//     17.9/20.0/18.1), ~255-260 TF/s achieved = ~88% of the legacy-path peak.
//     Only lever: halve HMMA count -> SINGLE-PASS fp16 both GEMMs.
//     Error model (calibrated x1.65 on R5): expect ~3.5e-4 << 1e-3.

#define MTOT 4096
#define DD   1024
#define BK   64
#define KSB  144                 // smem row stride bytes: 36 words -> conflict-free ldmatrix
#define STG_MAT  (128 * KSB)     // 18432 B per matrix tile
#define OFF_B    STG_MAT
#define STG_BYTES (2 * STG_MAT)  // 36864 B / stage
#define SMEM_SZ   (2 * STG_BYTES)   // 73728 B ; 2 CTAs/SM
#define NCHUNK   (DD / BK)       // 16

__device__ __half g_xh[MTOT * DD];
__device__ __half g_wvt[DD * DD];
__device__ __half g_wo[DD * DD];
__device__ __half g_vh[MTOT * DD];

// ------------------------------------------------------------------ asm utils
static __device__ __forceinline__ uint32_t smem_u32(const void* p) {
    uint32_t a;
    asm("{ .reg .u64 t; cvta.to.shared.u64 t, %1; cvt.u32.u64 %0, t; }" : "=r"(a) : "l"(p));
    return a;
}
#define CP16(s, g) \
    asm volatile("cp.async.cg.shared.global [%0], [%1], 16;" :: "r"(s), "l"(g))
#define CP_COMMIT() asm volatile("cp.async.commit_group;")
#define CP_WAIT0()  asm volatile("cp.async.wait_group 0;")

#define LDSM4(r, addr) \
    asm volatile("ldmatrix.sync.aligned.m8n8.x4.shared.b16 {%0,%1,%2,%3}, [%4];" \
                 : "=r"((r)[0]), "=r"((r)[1]), "=r"((r)[2]), "=r"((r)[3]) : "r"(addr))

#define MMA(d, a, b0, b1) \
    asm volatile("mma.sync.aligned.m16n8k16.row.col.f32.f16.f16.f32 " \
                 "{%0,%1,%2,%3}, {%4,%5,%6,%7}, {%8,%9}, {%0,%1,%2,%3};" \
                 : "+f"((d)[0]), "+f"((d)[1]), "+f"((d)[2]), "+f"((d)[3]) \
                 : "r"((a)[0]), "r"((a)[1]), "r"((a)[2]), "r"((a)[3]), "r"(b0), "r"(b1))

// ------------------------------------------------------------------ GEMM
// MODE 0: V = x @ WvT^T  (A = g_xh [m][k], B = g_wvt [n][k]) -> g_vh (fp16)
// MODE 1: out = gather(V) @ Wo^T (A gathered from g_vh, B = g_wo) -> fp32
template<int MODE>
__global__ void __launch_bounds__(128, 2)
gemm_hmma(float* __restrict__ outp) {
    extern __shared__ char smem[];
    const uint32_t sb = smem_u32(smem);

    const int tid  = threadIdx.x;
    const int lane = tid & 31, wid = tid >> 5;
    const int bm = blockIdx.y * 128;
    const int bn = blockIdx.x * 128;

    const __half* A_ = (MODE == 0) ? g_xh  : g_vh;
    const __half* B_ = (MODE == 0) ? g_wvt : g_wo;

    // gather constants (MODE 1): with BK=64 chunks, k>>6 == c exactly.
    const int boff = (bm >> 11) << 11;          // b * 2048
    const int hoff = ((bm & 2047) >> 7) * 64;   // h * 64

    // ---- global -> smem stage loader: 128 threads, 16 CP16 per thread
    const int seg  = tid & 7;        // 16B segment of 128B row
    const int row0 = tid >> 3;       // 0..15

    auto issue = [&](int c) {
        const uint32_t sbase = sb + (uint32_t)(c & 1) * STG_BYTES;
#pragma unroll
        for (int i = 0; i < 8; i++) {
            const int row = row0 + 16 * i;
            size_t aoff;
            if (MODE == 0) {
                aoff = (size_t)(bm + row) * DD + c * BK + seg * 8;
            } else {
                aoff = (size_t)(boff + row * 16 + c) * DD + hoff + seg * 8;
            }
            const size_t bo = (size_t)(bn + row) * DD + c * BK + seg * 8;
            CP16(sbase + row * KSB + seg * 16,         A_ + aoff);
            CP16(sbase + OFF_B + row * KSB + seg * 16, B_ + bo);
        }
        CP_COMMIT();
    };

    // ---- warp tiling: 2(m) x 2(n) warps of 64x64
    const int warp_m = (wid >> 1) * 64;
    const int warp_n = (wid & 1) * 64;
    const int lr = lane & 15;            // ldmatrix row within 16
    const int lcb = (lane >> 4) * 16;    // ldmatrix k-half byte offset

    float acc[4][8][4];
#pragma unroll
    for (int mt = 0; mt < 4; mt++)
#pragma unroll
        for (int j = 0; j < 8; j++)
#pragma unroll
            for (int q = 0; q < 4; q++) acc[mt][j][q] = 0.f;

    issue(0);

    for (int c = 0; c < NCHUNK; c++) {
        CP_WAIT0();
        __syncthreads();
        if (c + 1 < NCHUNK) issue(c + 1);   // after sync: stage readers all passed

        const uint32_t sbase = sb + (uint32_t)(c & 1) * STG_BYTES;
#pragma unroll
        for (int kk = 0; kk < 4; kk++) {
            const uint32_t kb = kk * 32 + lcb;  // k byte offset within 128B row

            // front-load fragments for this k16 step (8 independent LDSM)
            uint32_t aa[4][4], bb[4][4];
#pragma unroll
            for (int mt = 0; mt < 4; mt++)
                LDSM4(aa[mt], sbase + (warp_m + mt * 16 + lr) * KSB + kb);
#pragma unroll
            for (int nt = 0; nt < 4; nt++)
                LDSM4(bb[nt], sbase + OFF_B + (warp_n + nt * 16 + lr) * KSB + kb);

#pragma unroll
            for (int mt = 0; mt < 4; mt++)
#pragma unroll
                for (int nt = 0; nt < 4; nt++) {
                    MMA(acc[mt][2 * nt],     aa[mt], bb[nt][0], bb[nt][2]);
                    MMA(acc[mt][2 * nt + 1], aa[mt], bb[nt][1], bb[nt][3]);
                }
        }
    }

    // ---- epilogue (fragment layout: d0,d1 -> row lane>>2, d2,d3 -> +8)
#pragma unroll
    for (int mt = 0; mt < 4; mt++) {
        const int m0 = bm + warp_m + mt * 16 + (lane >> 2);
#pragma unroll
        for (int j = 0; j < 8; j++) {
            const int n0 = bn + warp_n + j * 8 + (lane & 3) * 2;
            const float* d = acc[mt][j];
            if (MODE == 0) {
#pragma unroll
                for (int half_ = 0; half_ < 2; half_++) {
                    const size_t o = (size_t)(m0 + 8 * half_) * DD + n0;
                    *(__half2*)&g_vh[o] =
                        __floats2half2_rn(d[2 * half_], d[2 * half_ + 1]);
                }
            } else {
#pragma unroll
                for (int half_ = 0; half_ < 2; half_++) {
                    const size_t o = (size_t)(m0 + 8 * half_) * DD + n0;
                    *(float2*)&outp[o] = make_float2(d[2 * half_], d[2 * half_ + 1]);
                }
            }
        }
    }
}

// ------------------------------------------------------------------ prep
__global__ void k_conv_x(const float* __restrict__ in) {
    const int i = blockIdx.x * 256 + threadIdx.x;   // over float4s
    float4 v = ((const float4*)in)[i];
    ((__half2*)g_xh)[2 * i]     = __floats2half2_rn(v.x, v.y);
    ((__half2*)g_xh)[2 * i + 1] = __floats2half2_rn(v.z, v.w);
}

__global__ void k_conv_wo(const float* __restrict__ in) {
    const int i = blockIdx.x * 256 + threadIdx.x;
    float4 v = ((const float4*)in)[i];
    ((__half2*)g_wo)[2 * i]     = __floats2half2_rn(v.x, v.y);
    ((__half2*)g_wo)[2 * i + 1] = __floats2half2_rn(v.z, v.w);
}

// WvT[n][k] = Wv[k][n], single fp16
__global__ void k_trans_wv(const float* __restrict__ W) {
    __shared__ float t[32][33];
    const int bx = blockIdx.x * 32, by = blockIdx.y * 32;
    const int tx = threadIdx.x, ty = threadIdx.y;   // (32, 8)
#pragma unroll
    for (int j = 0; j < 32; j += 8)
        t[ty + j][tx] = W[(size_t)(by + ty + j) * DD + bx + tx];
    __syncthreads();
#pragma unroll
    for (int j = 0; j < 32; j += 8) {
        const size_t o = (size_t)(bx + ty + j) * DD + by + tx;
        g_wvt[o] = __float2half_rn(t[tx][ty + j]);
    }
}

// ------------------------------------------------------------------ launch
// inputs: x, mask, Wq, Wk, Wv, Wo -> fp32 out [B,T,D]
extern "C" void kernel_launch(void* const* d_in, const int* in_sizes, int n_in,
                              void* d_out, int out_size) {
    const float* x  = (const float*)d_in[0];
    const float* Wv = (const float*)d_in[4];
    const float* Wo = (const float*)d_in[5];
    float* out = (float*)d_out;

    cudaFuncSetAttribute(gemm_hmma<0>, cudaFuncAttributeMaxDynamicSharedMemorySize, SMEM_SZ);
    cudaFuncSetAttribute(gemm_hmma<1>, cudaFuncAttributeMaxDynamicSharedMemorySize, SMEM_SZ);

    k_conv_x<<<(MTOT * DD / 4) / 256, 256>>>(x);
    k_trans_wv<<<dim3(32, 32), dim3(32, 8)>>>(Wv);
    k_conv_wo<<<(DD * DD / 4) / 256, 256>>>(Wo);

    dim3 grid(DD / 128, MTOT / 128);   // (8, 32) = 256 CTAs
    gemm_hmma<0><<<grid, 128, SMEM_SZ>>>(nullptr);
    gemm_hmma<1><<<grid, 128, SMEM_SZ>>>(out);
}

// round 9
// speedup vs baseline: 1.9593x; 1.0423x over previous
#include <cuda_runtime.h>
#include <cuda_fp16.h>
#include <cstdint>

// y = gather_perm(x @ Wv) @ Wo^T   (softmax rowsum == 1 collapse, validated R1)
// tcgen05 unavailable (harness targets sm_103, no 'a') => mma.sync path.
// Legacy HMMA ceiling: ~18-20 cyc/HMMA/SMSP invariant across R3-R8 configs;
// single-pass fp16 (R8) sits at the MAC-count floor (rel_err 4.15e-4).
// R9: 3-stage cp.async ring + wait_group 1 (hide chunk-copy latency),
//     fused single prep kernel (was 3 launches).

#define MTOT 4096
#define DD   1024
#define BK   64
#define KSB  144                 // smem row stride bytes: conflict-free ldmatrix
#define STG_MAT  (128 * KSB)     // 18432 B per matrix tile
#define OFF_B    STG_MAT
#define STG_BYTES (2 * STG_MAT)  // 36864 B / stage
#define NSTAGE   3
#define SMEM_SZ  (NSTAGE * STG_BYTES)  // 110592 B ; 2 CTAs/SM = 221 KB <= 228 KB
#define NCHUNK   (DD / BK)       // 16

__device__ __half g_xh[MTOT * DD];
__device__ __half g_wvt[DD * DD];
__device__ __half g_wo[DD * DD];
__device__ __half g_vh[MTOT * DD];

// ------------------------------------------------------------------ asm utils
static __device__ __forceinline__ uint32_t smem_u32(const void* p) {
    uint32_t a;
    asm("{ .reg .u64 t; cvta.to.shared.u64 t, %1; cvt.u32.u64 %0, t; }" : "=r"(a) : "l"(p));
    return a;
}
#define CP16(s, g) \
    asm volatile("cp.async.cg.shared.global [%0], [%1], 16;" :: "r"(s), "l"(g))
#define CP_COMMIT() asm volatile("cp.async.commit_group;")
#define CP_WAIT1()  asm volatile("cp.async.wait_group 1;")

#define LDSM4(r, addr) \
    asm volatile("ldmatrix.sync.aligned.m8n8.x4.shared.b16 {%0,%1,%2,%3}, [%4];" \
                 : "=r"((r)[0]), "=r"((r)[1]), "=r"((r)[2]), "=r"((r)[3]) : "r"(addr))

#define MMA(d, a, b0, b1) \
    asm volatile("mma.sync.aligned.m16n8k16.row.col.f32.f16.f16.f32 " \
                 "{%0,%1,%2,%3}, {%4,%5,%6,%7}, {%8,%9}, {%0,%1,%2,%3};" \
                 : "+f"((d)[0]), "+f"((d)[1]), "+f"((d)[2]), "+f"((d)[3]) \
                 : "r"((a)[0]), "r"((a)[1]), "r"((a)[2]), "r"((a)[3]), "r"(b0), "r"(b1))

// ------------------------------------------------------------------ GEMM
// MODE 0: V = x @ WvT^T  (A = g_xh [m][k], B = g_wvt [n][k]) -> g_vh (fp16)
// MODE 1: out = gather(V) @ Wo^T (A gathered from g_vh, B = g_wo) -> fp32
template<int MODE>
__global__ void __launch_bounds__(128, 2)
gemm_hmma(float* __restrict__ outp) {
    extern __shared__ char smem[];
    const uint32_t sb = smem_u32(smem);

    const int tid  = threadIdx.x;
    const int lane = tid & 31, wid = tid >> 5;
    const int bm = blockIdx.y * 128;
    const int bn = blockIdx.x * 128;

    const __half* A_ = (MODE == 0) ? g_xh  : g_vh;
    const __half* B_ = (MODE == 0) ? g_wvt : g_wo;

    // gather constants (MODE 1): with BK=64 chunks, k>>6 == c exactly.
    const int boff = (bm >> 11) << 11;          // b * 2048
    const int hoff = ((bm & 2047) >> 7) * 64;   // h * 64

    // ---- global -> smem stage loader: 128 threads, 16 CP16 per thread
    const int seg  = tid & 7;        // 16B segment of 128B row
    const int row0 = tid >> 3;       // 0..15

    auto issue = [&](int c) {
        const uint32_t sbase = sb + (uint32_t)(c % NSTAGE) * STG_BYTES;
#pragma unroll
        for (int i = 0; i < 8; i++) {
            const int row = row0 + 16 * i;
            size_t aoff;
            if (MODE == 0) {
                aoff = (size_t)(bm + row) * DD + c * BK + seg * 8;
            } else {
                aoff = (size_t)(boff + row * 16 + c) * DD + hoff + seg * 8;
            }
            const size_t bo = (size_t)(bn + row) * DD + c * BK + seg * 8;
            CP16(sbase + row * KSB + seg * 16,         A_ + aoff);
            CP16(sbase + OFF_B + row * KSB + seg * 16, B_ + bo);
        }
        CP_COMMIT();
    };

    // ---- warp tiling: 2(m) x 2(n) warps of 64x64
    const int warp_m = (wid >> 1) * 64;
    const int warp_n = (wid & 1) * 64;
    const int lr = lane & 15;            // ldmatrix row within 16
    const int lcb = (lane >> 4) * 16;    // ldmatrix k-half byte offset

    float acc[4][8][4];
#pragma unroll
    for (int mt = 0; mt < 4; mt++)
#pragma unroll
        for (int j = 0; j < 8; j++)
#pragma unroll
            for (int q = 0; q < 4; q++) acc[mt][j][q] = 0.f;

    issue(0);
    issue(1);

    for (int c = 0; c < NCHUNK; c++) {
        CP_WAIT1();          // groups complete in order -> group c done
        __syncthreads();
        // stage (c+2)%3 == (c-1)%3 was last read in compute(c-1); all warps
        // passed the barrier above, so overwrite is safe.
        if (c + 2 < NCHUNK) issue(c + 2);

        const uint32_t sbase = sb + (uint32_t)(c % NSTAGE) * STG_BYTES;
#pragma unroll
        for (int kk = 0; kk < 4; kk++) {
            const uint32_t kb = kk * 32 + lcb;  // k byte offset within 128B row

            uint32_t aa[4][4], bb[4][4];
#pragma unroll
            for (int mt = 0; mt < 4; mt++)
                LDSM4(aa[mt], sbase + (warp_m + mt * 16 + lr) * KSB + kb);
#pragma unroll
            for (int nt = 0; nt < 4; nt++)
                LDSM4(bb[nt], sbase + OFF_B + (warp_n + nt * 16 + lr) * KSB + kb);

#pragma unroll
            for (int mt = 0; mt < 4; mt++)
#pragma unroll
                for (int nt = 0; nt < 4; nt++) {
                    MMA(acc[mt][2 * nt],     aa[mt], bb[nt][0], bb[nt][2]);
                    MMA(acc[mt][2 * nt + 1], aa[mt], bb[nt][1], bb[nt][3]);
                }
        }
    }

    // ---- epilogue (fragment layout: d0,d1 -> row lane>>2, d2,d3 -> +8)
#pragma unroll
    for (int mt = 0; mt < 4; mt++) {
        const int m0 = bm + warp_m + mt * 16 + (lane >> 2);
#pragma unroll
        for (int j = 0; j < 8; j++) {
            const int n0 = bn + warp_n + j * 8 + (lane & 3) * 2;
            const float* d = acc[mt][j];
            if (MODE == 0) {
#pragma unroll
                for (int half_ = 0; half_ < 2; half_++) {
                    const size_t o = (size_t)(m0 + 8 * half_) * DD + n0;
                    *(__half2*)&g_vh[o] =
                        __floats2half2_rn(d[2 * half_], d[2 * half_ + 1]);
                }
            } else {
#pragma unroll
                for (int half_ = 0; half_ < 2; half_++) {
                    const size_t o = (size_t)(m0 + 8 * half_) * DD + n0;
                    *(float2*)&outp[o] = make_float2(d[2 * half_], d[2 * half_ + 1]);
                }
            }
        }
    }
}

// ------------------------------------------------------------------ fused prep
// blocks [0,4096): x fp32->fp16    (1M float4, 256/block)
// blocks [4096,5120): Wo convert (256 float4/block) + WvT transpose tile
__global__ void k_prep(const float* __restrict__ x,
                       const float* __restrict__ Wv,
                       const float* __restrict__ Wo) {
    const int blk = blockIdx.x;
    if (blk < 4096) {
        const int i = blk * 256 + threadIdx.x;
        float4 v = ((const float4*)x)[i];
        ((__half2*)g_xh)[2 * i]     = __floats2half2_rn(v.x, v.y);
        ((__half2*)g_xh)[2 * i + 1] = __floats2half2_rn(v.z, v.w);
    } else {
        const int t = blk - 4096;   // 0..1023
        // Wo convert
        const int i = t * 256 + threadIdx.x;
        float4 v = ((const float4*)Wo)[i];
        ((__half2*)g_wo)[2 * i]     = __floats2half2_rn(v.x, v.y);
        ((__half2*)g_wo)[2 * i + 1] = __floats2half2_rn(v.z, v.w);
        // WvT[n][k] = Wv[k][n] for one 32x32 tile
        __shared__ float tt[32][33];
        const int bx = (t & 31) * 32, by = (t >> 5) * 32;
        const int tx = threadIdx.x & 31, ty = threadIdx.x >> 5;  // 32 x 8
#pragma unroll
        for (int j = 0; j < 32; j += 8)
            tt[ty + j][tx] = Wv[(size_t)(by + ty + j) * DD + bx + tx];
        __syncthreads();
#pragma unroll
        for (int j = 0; j < 32; j += 8)
            g_wvt[(size_t)(bx + ty + j) * DD + by + tx] =
                __float2half_rn(tt[tx][ty + j]);
    }
}

// ------------------------------------------------------------------ launch
// inputs: x, mask, Wq, Wk, Wv, Wo -> fp32 out [B,T,D]
extern "C" void kernel_launch(void* const* d_in, const int* in_sizes, int n_in,
                              void* d_out, int out_size) {
    const float* x  = (const float*)d_in[0];
    const float* Wv = (const float*)d_in[4];
    const float* Wo = (const float*)d_in[5];
    float* out = (float*)d_out;

    cudaFuncSetAttribute(gemm_hmma<0>, cudaFuncAttributeMaxDynamicSharedMemorySize, SMEM_SZ);
    cudaFuncSetAttribute(gemm_hmma<1>, cudaFuncAttributeMaxDynamicSharedMemorySize, SMEM_SZ);

    k_prep<<<5120, 256>>>(x, Wv, Wo);

    dim3 grid(DD / 128, MTOT / 128);   // (8, 32) = 256 CTAs
    gemm_hmma<0><<<grid, 128, SMEM_SZ>>>(nullptr);
    gemm_hmma<1><<<grid, 128, SMEM_SZ>>>(out);
}